// round 15
// baseline (speedup 1.0000x reference)
#include <cuda_runtime.h>
#include <cuda_bf16.h>
#include <math.h>
#include <stdint.h>

#define BB   8192
#define NX   2048
#define NH   512
#define NY   1024

// Scratch (no allocations allowed in kernel_launch)
__device__ __nv_bfloat16 g_xb[(size_t)BB * NX];    // relu(x) in bf16
__device__ __nv_bfloat16 g_wfcb[(size_t)NH * NX];  // W_fc in bf16
__device__ __nv_bfloat16 g_wqb[(size_t)NY * NH];   // W_q in bf16
__device__ __nv_bfloat16 g_hb[(size_t)BB * NH];    // hidden activations bf16
__device__ float g_hpart[(size_t)BB * 8];          // per-(row, 64-coltile) sum h^2
__device__ float g_spart[(size_t)BB * 32];         // per-(row, 32-coltile) sum 1/(1+d)
__device__ float g_wqnorm[NY];                     // ||w_j||^2

// ---------------------------------------------------------------------------
static __device__ __forceinline__ uint32_t smem_u32(const void* p) {
    uint32_t a;
    asm("{ .reg .u64 t; cvta.to.shared.u64 t, %1; cvt.u32.u64 %0, t; }"
        : "=r"(a) : "l"(p));
    return a;
}

#define LDSM_X4(r0, r1, r2, r3, a)                                           \
    asm volatile("ldmatrix.sync.aligned.m8n8.x4.shared.b16 {%0,%1,%2,%3}, [%4];" \
                 : "=r"(r0), "=r"(r1), "=r"(r2), "=r"(r3) : "r"(a))

#define CP16(s, g)                                                           \
    asm volatile("cp.async.cg.shared.global [%0], [%1], 16;" :: "r"(s), "l"(g))
#define CP_COMMIT() asm volatile("cp.async.commit_group;" ::: "memory")
#define CP_WAIT1()  asm volatile("cp.async.wait_group 1;"  ::: "memory")

// PDL: producer signals dependents may start; consumer waits for producer's
// memory to be visible. No-ops when launched without the PDL attribute.
#define GDC_LAUNCH() asm volatile("griddepcontrol.launch_dependents;" ::: "memory")
#define GDC_WAIT()   asm volatile("griddepcontrol.wait;" ::: "memory")

static __device__ __forceinline__ float frcp(float x) {
    float r;
    asm("rcp.approx.f32 %0, %1;" : "=f"(r) : "f"(x));
    return r;
}

static __device__ __forceinline__ void mma16(float* c, const uint32_t* a,
                                             uint32_t b0, uint32_t b1) {
    asm volatile(
        "mma.sync.aligned.m16n8k16.row.col.f32.bf16.bf16.f32 "
        "{%0,%1,%2,%3}, {%4,%5,%6,%7}, {%8,%9}, {%0,%1,%2,%3};"
        : "+f"(c[0]), "+f"(c[1]), "+f"(c[2]), "+f"(c[3])
        : "r"(a[0]), "r"(a[1]), "r"(a[2]), "r"(a[3]), "r"(b0), "r"(b1));
}

static __device__ __forceinline__ uint32_t pack_bf16(float lo, float hi) {
    __nv_bfloat162 v = __floats2bfloat162_rn(lo, hi);  // .x = low half
    return *(uint32_t*)&v;
}

#define TILE_BYTES  16384               // 128 rows x 128B
#define STAGE_BYTES 32768               // A + B
#define NSTAGE      3
#define DSMEM_BYTES (NSTAGE * STAGE_BYTES + 512)

// ---------------------------------------------------------------------------
// GEMM1: h = relu(A@B^T + bias). 4 warps (2m x 2n), warp tile 64x64,
// CTA 128x128, BK=64, cp.async 3-stage pipeline. (proven config)
// Writes bf16 h and per-row partial sums of bf16(h)^2 (8 per row).
// ---------------------------------------------------------------------------
__global__ __launch_bounds__(128, 2)
void tgemm1(const __nv_bfloat16* __restrict__ A, const __nv_bfloat16* __restrict__ Bm,
            const float* __restrict__ prm, float* __restrict__ hpart,
            __nv_bfloat16* __restrict__ C, int M, int N, int K)
{
    extern __shared__ char smem[];
    const uint32_t sbase = smem_u32(smem);

    const int tid  = threadIdx.x;
    const int bn   = blockIdx.x, bm = blockIdx.y;
    const int warp = tid >> 5, lane = tid & 31;
    const int wm   = warp & 1;
    const int wn   = warp >> 1;         // 0..1
    const int rm   = lane & 7;

    const int kha = lane >> 4;
    const int khb = (lane >> 3) & 1;
    int rowA[4], rowB[4];
    #pragma unroll
    for (int mi = 0; mi < 4; mi++)
        rowA[mi] = wm * 64 + mi * 16 + ((lane >> 3) & 1) * 8 + rm;
    #pragma unroll
    for (int pp = 0; pp < 4; pp++)
        rowB[pp] = wn * 64 + pp * 16 + ((lane >> 4) & 1) * 8 + rm;

    float acc[4][8][4];
    #pragma unroll
    for (int i = 0; i < 4; i++)
        #pragma unroll
        for (int j = 0; j < 8; j++)
            #pragma unroll
            for (int q = 0; q < 4; q++) acc[i][j][q] = 0.f;

    const int KT = K >> 6;
    const int r0 = tid >> 3;
    const int c4 = tid & 7;

    auto issue_copy = [&](int kt, int buf) {
        const uint32_t sa = sbase + buf * STAGE_BYTES;
        const uint32_t sb = sa + TILE_BYTES;
        const __nv_bfloat16* ag = A  + (size_t)(bm * 128 + r0) * K + kt * 64 + c4 * 8;
        const __nv_bfloat16* bg = Bm + (size_t)(bn * 128 + r0) * K + kt * 64 + c4 * 8;
        #pragma unroll
        for (int p = 0; p < 8; p++) {
            const int row = r0 + p * 16;
            const uint32_t soff = row * 128 + ((c4 ^ (row & 7)) * 16);
            CP16(sa + soff, ag + (size_t)p * 16 * K);
            CP16(sb + soff, bg + (size_t)p * 16 * K);
        }
    };

    auto compute = [&](int buf) {
        const uint32_t Sa = sbase + buf * STAGE_BYTES;
        const uint32_t Sb = Sa + TILE_BYTES;
        #pragma unroll
        for (int ks = 0; ks < 4; ks++) {
            uint32_t a[4][4], b[4][4];
            #pragma unroll
            for (int mi = 0; mi < 4; mi++) {
                const uint32_t addr = Sa + rowA[mi] * 128 + (((2*ks + kha) ^ rm) * 16);
                LDSM_X4(a[mi][0], a[mi][1], a[mi][2], a[mi][3], addr);
            }
            #pragma unroll
            for (int pp = 0; pp < 4; pp++) {
                const uint32_t addr = Sb + rowB[pp] * 128 + (((2*ks + khb) ^ rm) * 16);
                LDSM_X4(b[pp][0], b[pp][1], b[pp][2], b[pp][3], addr);
            }
            #pragma unroll
            for (int mi = 0; mi < 4; mi++)
                #pragma unroll
                for (int nj = 0; nj < 8; nj++)
                    mma16(acc[mi][nj], a[mi],
                          b[nj >> 1][(nj & 1) * 2], b[nj >> 1][(nj & 1) * 2 + 1]);
        }
    };

    GDC_WAIT();                         // inputs from convert_all visible
    issue_copy(0, 0); CP_COMMIT();
    issue_copy(1, 1); CP_COMMIT();
    int buf = 0;
    for (int kt = 0; kt < KT; kt++) {
        CP_WAIT1();
        __syncthreads();
        if (kt + 2 < KT) issue_copy(kt + 2, (buf + 2) % NSTAGE);
        CP_COMMIT();
        compute(buf);
        buf = (buf + 1) % NSTAGE;
    }

    const int gr0 = bm * 128 + wm * 64 + (lane >> 2);
    const int gc0 = bn * 128 + wn * 64 + (lane & 3) * 2;
    #pragma unroll
    for (int mi = 0; mi < 4; mi++) {
        #pragma unroll
        for (int half = 0; half < 2; half++) {
            const int row = gr0 + mi * 16 + half * 8;
            float s = 0.f;
            #pragma unroll
            for (int nj = 0; nj < 8; nj++) {
                const int col = gc0 + nj * 8;
                const float v0 = acc[mi][nj][half * 2 + 0];
                const float v1 = acc[mi][nj][half * 2 + 1];
                const __nv_bfloat162 hp = __floats2bfloat162_rn(
                    fmaxf(v0 + prm[col + 0], 0.f),
                    fmaxf(v1 + prm[col + 1], 0.f));
                *(uint32_t*)(C + (size_t)row * N + col) = *(const uint32_t*)&hp;
                const float2 hf = __bfloat1622float2(hp);
                s = fmaf(hf.x, hf.x, fmaf(hf.y, hf.y, s));
            }
            s += __shfl_xor_sync(0xFFFFFFFFu, s, 1);
            s += __shfl_xor_sync(0xFFFFFFFFu, s, 2);
            if ((lane & 3) == 0)
                hpart[(size_t)row * 8 + bn * 2 + wn] = s;
        }
    }
    GDC_LAUNCH();
}

// ---------------------------------------------------------------------------
// GEMM2: t = -log(1 + max(||h||^2 - 2 h@Wq^T + ||w||^2, 0))
// 8 warps (2m x 4n, warp tile 64x32), CTA 128x128, MSUB=2 M-tiles per CTA.
// ||h||^2 finished in-kernel from hpart (8 partials/row) into smem.
// Epilogue also writes per-(row, 32-col slice) partials of sum 1/(1+d)
// ( = sum exp(t) ) into spart[row*32 + bn*4 + wn] for the lse pass.
// ---------------------------------------------------------------------------
#define MSUB2 2
__global__ __launch_bounds__(256, 2)
void tgemm2(const __nv_bfloat16* __restrict__ A, const __nv_bfloat16* __restrict__ Bm,
            const float* __restrict__ prm, const float* __restrict__ hpart,
            float* __restrict__ spart, float* __restrict__ C, int M, int N, int K)
{
    extern __shared__ char smem[];
    const uint32_t sbase = smem_u32(smem);
    float* rn_s = (float*)(smem + NSTAGE * STAGE_BYTES);   // 128 floats

    const int tid  = threadIdx.x;
    const int bn   = blockIdx.x;
    const int warp = tid >> 5, lane = tid & 31;
    const int wm   = warp & 1;
    const int wn   = warp >> 1;         // 0..3
    const int rm   = lane & 7;

    const int kha = lane >> 4;
    const int khb = (lane >> 3) & 1;
    int rowA[4], rowB[2];
    #pragma unroll
    for (int mi = 0; mi < 4; mi++)
        rowA[mi] = wm * 64 + mi * 16 + ((lane >> 3) & 1) * 8 + rm;
    #pragma unroll
    for (int pp = 0; pp < 2; pp++)
        rowB[pp] = wn * 32 + pp * 16 + ((lane >> 4) & 1) * 8 + rm;

    const int KT = K >> 6;
    const int r0 = tid >> 3;
    const int c4 = tid & 7;

    GDC_WAIT();                         // h, hpart from tgemm1 visible

    for (int sub = 0; sub < MSUB2; sub++) {
        const int bm = blockIdx.y * MSUB2 + sub;
        __syncthreads();                // protect stage buffers + rn_s

        if (tid < 128) {
            const float4* pp = (const float4*)(hpart + (size_t)(bm * 128 + tid) * 8);
            const float4 a = pp[0], b = pp[1];
            rn_s[tid] = ((a.x + a.y) + (a.z + a.w)) + ((b.x + b.y) + (b.z + b.w));
        }

        float acc[4][4][4];
        #pragma unroll
        for (int i = 0; i < 4; i++)
            #pragma unroll
            for (int j = 0; j < 4; j++)
                #pragma unroll
                for (int q = 0; q < 4; q++) acc[i][j][q] = 0.f;

        auto issue_copy = [&](int kt, int buf) {
            const uint32_t sa = sbase + buf * STAGE_BYTES;
            const uint32_t sb = sa + TILE_BYTES;
            const __nv_bfloat16* ag = A  + (size_t)(bm * 128 + r0) * K + kt * 64 + c4 * 8;
            const __nv_bfloat16* bg = Bm + (size_t)(bn * 128 + r0) * K + kt * 64 + c4 * 8;
            #pragma unroll
            for (int p = 0; p < 4; p++) {
                const int row = r0 + p * 32;
                const uint32_t soff = row * 128 + ((c4 ^ (row & 7)) * 16);
                CP16(sa + soff, ag + (size_t)p * 32 * K);
                CP16(sb + soff, bg + (size_t)p * 32 * K);
            }
        };

        auto compute = [&](int buf) {
            const uint32_t Sa = sbase + buf * STAGE_BYTES;
            const uint32_t Sb = Sa + TILE_BYTES;
            #pragma unroll
            for (int ks = 0; ks < 4; ks++) {
                uint32_t a[4][4], b[2][4];
                #pragma unroll
                for (int mi = 0; mi < 4; mi++) {
                    const uint32_t addr = Sa + rowA[mi] * 128 + (((2*ks + kha) ^ rm) * 16);
                    LDSM_X4(a[mi][0], a[mi][1], a[mi][2], a[mi][3], addr);
                }
                #pragma unroll
                for (int pp = 0; pp < 2; pp++) {
                    const uint32_t addr = Sb + rowB[pp] * 128 + (((2*ks + khb) ^ rm) * 16);
                    LDSM_X4(b[pp][0], b[pp][1], b[pp][2], b[pp][3], addr);
                }
                #pragma unroll
                for (int mi = 0; mi < 4; mi++)
                    #pragma unroll
                    for (int nj = 0; nj < 4; nj++)
                        mma16(acc[mi][nj], a[mi],
                              b[nj >> 1][(nj & 1) * 2], b[nj >> 1][(nj & 1) * 2 + 1]);
            }
        };

        issue_copy(0, 0); CP_COMMIT();
        issue_copy(1, 1); CP_COMMIT();
        int buf = 0;
        for (int kt = 0; kt < KT; kt++) {
            CP_WAIT1();
            __syncthreads();            // also orders rn_s before epilogue
            if (kt + 2 < KT) issue_copy(kt + 2, (buf + 2) % NSTAGE);
            CP_COMMIT();
            compute(buf);
            buf = (buf + 1) % NSTAGE;
        }

        const int lr0 = wm * 64 + (lane >> 2);
        const int gc0 = bn * 128 + wn * 32 + (lane & 3) * 2;
        #pragma unroll
        for (int mi = 0; mi < 4; mi++) {
            #pragma unroll
            for (int half = 0; half < 2; half++) {
                const int lrow = lr0 + mi * 16 + half * 8;
                const int row  = bm * 128 + lrow;
                const float rn = rn_s[lrow];
                float* crow = C + (size_t)row * N;
                float se = 0.f;              // partial sum of 1/(1+d) = exp(t)
                #pragma unroll
                for (int nj = 0; nj < 4; nj++) {
                    const int col = gc0 + nj * 8;
                    const float v0 = acc[mi][nj][half * 2 + 0];
                    const float v1 = acc[mi][nj][half * 2 + 1];
                    const float p0 = 1.f + fmaxf(fmaf(-2.f, v0, rn + prm[col + 0]), 0.f);
                    const float p1 = 1.f + fmaxf(fmaf(-2.f, v1, rn + prm[col + 1]), 0.f);
                    float2 o = { -__logf(p0), -__logf(p1) };
                    se += frcp(p0) + frcp(p1);
                    *(float2*)(crow + col) = o;
                }
                se += __shfl_xor_sync(0xFFFFFFFFu, se, 1);
                se += __shfl_xor_sync(0xFFFFFFFFu, se, 2);
                if ((lane & 3) == 0)
                    spart[(size_t)row * 32 + bn * 4 + wn] = se;
            }
        }
    }
    GDC_LAUNCH();
}

// ---------------------------------------------------------------------------
// Merged fp32->bf16 conversion, 16 elems/thread: x (relu), W_fc, W_q.
// W_q: one warp covers exactly one row (32 lanes x 16 = 512) -> shfl norm.
// Region boundaries are multiples of 4096 elements; blocks never straddle.
// ---------------------------------------------------------------------------
#define NXB_E ((size_t)BB * NX)
#define NFC_E ((size_t)NH * NX)
#define NWQ_E ((size_t)NY * NH)

__global__ __launch_bounds__(256)
void convert_all(const float* __restrict__ x, const float* __restrict__ wfc,
                 const float* __restrict__ wq, __nv_bfloat16* __restrict__ xb,
                 __nv_bfloat16* __restrict__ wfcb, __nv_bfloat16* __restrict__ wqb,
                 float* __restrict__ wqn)
{
    const int tid = threadIdx.x;
    const size_t i = (size_t)blockIdx.x * blockDim.x + tid;
    const size_t e = i * 16;
    const float* src;
    __nv_bfloat16* dst;
    bool relu = false, iswq = false;
    size_t local = 0;
    if (e < NXB_E)              { src = x   + e;           dst = xb   + e;           relu = true; }
    else if (e < NXB_E + NFC_E) { src = wfc + (e - NXB_E); dst = wfcb + (e - NXB_E); }
    else { local = e - NXB_E - NFC_E; src = wq + local; dst = wqb + local; iswq = true; }

    float4 a0 = ((const float4*)src)[0];
    float4 a1 = ((const float4*)src)[1];
    float4 a2 = ((const float4*)src)[2];
    float4 a3 = ((const float4*)src)[3];
    if (relu) {
        a0.x = fmaxf(a0.x, 0.f); a0.y = fmaxf(a0.y, 0.f);
        a0.z = fmaxf(a0.z, 0.f); a0.w = fmaxf(a0.w, 0.f);
        a1.x = fmaxf(a1.x, 0.f); a1.y = fmaxf(a1.y, 0.f);
        a1.z = fmaxf(a1.z, 0.f); a1.w = fmaxf(a1.w, 0.f);
        a2.x = fmaxf(a2.x, 0.f); a2.y = fmaxf(a2.y, 0.f);
        a2.z = fmaxf(a2.z, 0.f); a2.w = fmaxf(a2.w, 0.f);
        a3.x = fmaxf(a3.x, 0.f); a3.y = fmaxf(a3.y, 0.f);
        a3.z = fmaxf(a3.z, 0.f); a3.w = fmaxf(a3.w, 0.f);
    }
    uint4 o0 = { pack_bf16(a0.x, a0.y), pack_bf16(a0.z, a0.w),
                 pack_bf16(a1.x, a1.y), pack_bf16(a1.z, a1.w) };
    uint4 o1 = { pack_bf16(a2.x, a2.y), pack_bf16(a2.z, a2.w),
                 pack_bf16(a3.x, a3.y), pack_bf16(a3.z, a3.w) };
    ((uint4*)dst)[0] = o0;
    ((uint4*)dst)[1] = o1;

    if (iswq) {
        float s = 0.f;
        #pragma unroll
        for (int q = 0; q < 4; q++) {
            const float2 v0 = __bfloat1622float2(*(const __nv_bfloat162*)&(&o0.x)[q]);
            const float2 v1 = __bfloat1622float2(*(const __nv_bfloat162*)&(&o1.x)[q]);
            s = fmaf(v0.x, v0.x, fmaf(v0.y, v0.y, s));
            s = fmaf(v1.x, v1.x, fmaf(v1.y, v1.y, s));
        }
        #pragma unroll
        for (int off = 16; off; off >>= 1)
            s += __shfl_xor_sync(0xFFFFFFFFu, s, off);
        if ((tid & 31) == 0)
            wqn[local >> 9] = s;        // 512 elems per W_q row = 1 warp
    }
    GDC_LAUNCH();
}

// ---------------------------------------------------------------------------
// lse: warp per row. Row sums of exp(t) precomputed by GEMM2 (spart, 32
// partials/row) -> pure streaming subtract: t -= log(sum). No exp here.
// ---------------------------------------------------------------------------
__global__ __launch_bounds__(256)
void lse_kernel(float* __restrict__ T, const float* __restrict__ spart)
{
    const int warp = threadIdx.x >> 5, lane = threadIdx.x & 31;
    const int row  = blockIdx.x * 8 + warp;
    float* t = T + (size_t)row * NY;

    GDC_WAIT();

    float s = spart[(size_t)row * 32 + lane];
    #pragma unroll
    for (int o = 16; o; o >>= 1) s += __shfl_xor_sync(0xFFFFFFFFu, s, o);
    const float lse = logf(s);

    float4 v[8];
    #pragma unroll
    for (int i = 0; i < 8; i++)
        v[i] = *(const float4*)(t + (lane + i * 32) * 4);
    #pragma unroll
    for (int i = 0; i < 8; i++) {
        float4 o4 = { v[i].x - lse, v[i].y - lse, v[i].z - lse, v[i].w - lse };
        *(float4*)(t + (lane + i * 32) * 4) = o4;
    }
}

// ---------------------------------------------------------------------------
extern "C" void kernel_launch(void* const* d_in, const int* in_sizes, int n_in,
                              void* d_out, int out_size)
{
    const float* x    = (const float*)d_in[0];   // [B, Nx]
    const float* W_fc = (const float*)d_in[1];   // [Nh, Nx]
    const float* b_fc = (const float*)d_in[2];   // [Nh]
    const float* W_q  = (const float*)d_in[3];   // [Ny, Nh]
    float* out = (float*)d_out;                  // [B, Ny]

    void* p;
    cudaGetSymbolAddress(&p, g_xb);     __nv_bfloat16* xb   = (__nv_bfloat16*)p;
    cudaGetSymbolAddress(&p, g_wfcb);   __nv_bfloat16* wfcb = (__nv_bfloat16*)p;
    cudaGetSymbolAddress(&p, g_wqb);    __nv_bfloat16* wqb  = (__nv_bfloat16*)p;
    cudaGetSymbolAddress(&p, g_hb);     __nv_bfloat16* hb   = (__nv_bfloat16*)p;
    cudaGetSymbolAddress(&p, g_hpart);  float* hp  = (float*)p;
    cudaGetSymbolAddress(&p, g_spart);  float* sp  = (float*)p;
    cudaGetSymbolAddress(&p, g_wqnorm); float* wqn = (float*)p;

    cudaFuncSetAttribute(tgemm1, cudaFuncAttributeMaxDynamicSharedMemorySize, DSMEM_BYTES);
    cudaFuncSetAttribute(tgemm2, cudaFuncAttributeMaxDynamicSharedMemorySize, DSMEM_BYTES);

    cudaLaunchAttribute pdl[1];
    pdl[0].id = cudaLaunchAttributeProgrammaticStreamSerialization;
    pdl[0].val.programmaticStreamSerializationAllowed = 1;

    // 0) convert all inputs to bf16 (relu fused into x; wq norms fused)
    {
        const size_t total = NXB_E + NFC_E + NWQ_E;
        convert_all<<<(unsigned)(total / 4096), 256>>>(x, W_fc, W_q, xb, wfcb, wqb, wqn);
    }
    // 1) h = relu(xb @ wfcb^T + b_fc) -> bf16, plus ||h||^2 partials [PDL]
    {
        cudaLaunchConfig_t cfg = {};
        cfg.gridDim  = dim3(NH / 128, BB / 128, 1);
        cfg.blockDim = dim3(128, 1, 1);
        cfg.dynamicSmemBytes = DSMEM_BYTES;
        cfg.attrs = pdl; cfg.numAttrs = 1;
        cudaLaunchKernelEx(&cfg, tgemm1,
                           (const __nv_bfloat16*)xb, (const __nv_bfloat16*)wfcb,
                           (const float*)b_fc, hp, hb, (int)BB, (int)NH, (int)NX);
    }
    // 2) t = -log(1 + d), plus per-row exp-sum partials [PDL]
    {
        cudaLaunchConfig_t cfg = {};
        cfg.gridDim  = dim3(NY / 128, BB / 256, 1);
        cfg.blockDim = dim3(256, 1, 1);
        cfg.dynamicSmemBytes = DSMEM_BYTES;
        cfg.attrs = pdl; cfg.numAttrs = 1;
        cudaLaunchKernelEx(&cfg, tgemm2,
                           (const __nv_bfloat16*)hb, (const __nv_bfloat16*)wqb,
                           (const float*)wqn, (const float*)hp, sp, out,
                           (int)BB, (int)NY, (int)NH);
    }
    // 3) log-softmax normalization: pure subtract stream [PDL]
    {
        cudaLaunchConfig_t cfg = {};
        cfg.gridDim  = dim3(BB / 8, 1, 1);
        cfg.blockDim = dim3(256, 1, 1);
        cfg.attrs = pdl; cfg.numAttrs = 1;
        cudaLaunchKernelEx(&cfg, lse_kernel, out, (const float*)sp);
    }
}

// round 16
// speedup vs baseline: 1.0354x; 1.0354x over previous
#include <cuda_runtime.h>
#include <cuda_bf16.h>
#include <math.h>
#include <stdint.h>

#define BB   8192
#define NX   2048
#define NH   512
#define NY   1024

// Scratch (no allocations allowed in kernel_launch)
__device__ __nv_bfloat16 g_xb[(size_t)BB * NX];    // relu(x) in bf16
__device__ __nv_bfloat16 g_wfcb[(size_t)NH * NX];  // W_fc in bf16
__device__ __nv_bfloat16 g_wqb[(size_t)NY * NH];   // W_q in bf16
__device__ __nv_bfloat16 g_hb[(size_t)BB * NH];    // hidden activations bf16
__device__ float g_hpart[(size_t)BB * 8];          // per-(row, 64-coltile) sum h^2
__device__ float g_wqnorm[NY];                     // ||w_j||^2

// ---------------------------------------------------------------------------
static __device__ __forceinline__ uint32_t smem_u32(const void* p) {
    uint32_t a;
    asm("{ .reg .u64 t; cvta.to.shared.u64 t, %1; cvt.u32.u64 %0, t; }"
        : "=r"(a) : "l"(p));
    return a;
}

#define LDSM_X4(r0, r1, r2, r3, a)                                           \
    asm volatile("ldmatrix.sync.aligned.m8n8.x4.shared.b16 {%0,%1,%2,%3}, [%4];" \
                 : "=r"(r0), "=r"(r1), "=r"(r2), "=r"(r3) : "r"(a))

#define CP16(s, g)                                                           \
    asm volatile("cp.async.cg.shared.global [%0], [%1], 16;" :: "r"(s), "l"(g))
#define CP_COMMIT() asm volatile("cp.async.commit_group;" ::: "memory")
#define CP_WAIT1()  asm volatile("cp.async.wait_group 1;"  ::: "memory")

// PDL: producer signals dependents may start; consumer waits for producer's
// memory to be visible. No-ops when launched without the PDL attribute.
#define GDC_LAUNCH() asm volatile("griddepcontrol.launch_dependents;" ::: "memory")
#define GDC_WAIT()   asm volatile("griddepcontrol.wait;" ::: "memory")

static __device__ __forceinline__ void mma16(float* c, const uint32_t* a,
                                             uint32_t b0, uint32_t b1) {
    asm volatile(
        "mma.sync.aligned.m16n8k16.row.col.f32.bf16.bf16.f32 "
        "{%0,%1,%2,%3}, {%4,%5,%6,%7}, {%8,%9}, {%0,%1,%2,%3};"
        : "+f"(c[0]), "+f"(c[1]), "+f"(c[2]), "+f"(c[3])
        : "r"(a[0]), "r"(a[1]), "r"(a[2]), "r"(a[3]), "r"(b0), "r"(b1));
}

static __device__ __forceinline__ uint32_t pack_bf16(float lo, float hi) {
    __nv_bfloat162 v = __floats2bfloat162_rn(lo, hi);  // .x = low half
    return *(uint32_t*)&v;
}

#define TILE_BYTES  16384               // 128 rows x 128B
#define STAGE_BYTES 32768               // A + B
#define NSTAGE      3
#define DSMEM_BYTES (NSTAGE * STAGE_BYTES + 512)

// ---------------------------------------------------------------------------
// GEMM1: h = relu(A@B^T + bias). 4 warps (2m x 2n), warp tile 64x64,
// CTA 128x128, BK=64, cp.async 3-stage pipeline. (proven config)
// Writes bf16 h and per-row partial sums of bf16(h)^2 (8 per row).
// ---------------------------------------------------------------------------
__global__ __launch_bounds__(128, 2)
void tgemm1(const __nv_bfloat16* __restrict__ A, const __nv_bfloat16* __restrict__ Bm,
            const float* __restrict__ prm, float* __restrict__ hpart,
            __nv_bfloat16* __restrict__ C, int M, int N, int K)
{
    extern __shared__ char smem[];
    const uint32_t sbase = smem_u32(smem);

    const int tid  = threadIdx.x;
    const int bn   = blockIdx.x, bm = blockIdx.y;
    const int warp = tid >> 5, lane = tid & 31;
    const int wm   = warp & 1;
    const int wn   = warp >> 1;         // 0..1
    const int rm   = lane & 7;

    const int kha = lane >> 4;
    const int khb = (lane >> 3) & 1;
    int rowA[4], rowB[4];
    #pragma unroll
    for (int mi = 0; mi < 4; mi++)
        rowA[mi] = wm * 64 + mi * 16 + ((lane >> 3) & 1) * 8 + rm;
    #pragma unroll
    for (int pp = 0; pp < 4; pp++)
        rowB[pp] = wn * 64 + pp * 16 + ((lane >> 4) & 1) * 8 + rm;

    float acc[4][8][4];
    #pragma unroll
    for (int i = 0; i < 4; i++)
        #pragma unroll
        for (int j = 0; j < 8; j++)
            #pragma unroll
            for (int q = 0; q < 4; q++) acc[i][j][q] = 0.f;

    const int KT = K >> 6;
    const int r0 = tid >> 3;
    const int c4 = tid & 7;

    auto issue_copy = [&](int kt, int buf) {
        const uint32_t sa = sbase + buf * STAGE_BYTES;
        const uint32_t sb = sa + TILE_BYTES;
        const __nv_bfloat16* ag = A  + (size_t)(bm * 128 + r0) * K + kt * 64 + c4 * 8;
        const __nv_bfloat16* bg = Bm + (size_t)(bn * 128 + r0) * K + kt * 64 + c4 * 8;
        #pragma unroll
        for (int p = 0; p < 8; p++) {
            const int row = r0 + p * 16;
            const uint32_t soff = row * 128 + ((c4 ^ (row & 7)) * 16);
            CP16(sa + soff, ag + (size_t)p * 16 * K);
            CP16(sb + soff, bg + (size_t)p * 16 * K);
        }
    };

    auto compute = [&](int buf) {
        const uint32_t Sa = sbase + buf * STAGE_BYTES;
        const uint32_t Sb = Sa + TILE_BYTES;
        #pragma unroll
        for (int ks = 0; ks < 4; ks++) {
            uint32_t a[4][4], b[4][4];
            #pragma unroll
            for (int mi = 0; mi < 4; mi++) {
                const uint32_t addr = Sa + rowA[mi] * 128 + (((2*ks + kha) ^ rm) * 16);
                LDSM_X4(a[mi][0], a[mi][1], a[mi][2], a[mi][3], addr);
            }
            #pragma unroll
            for (int pp = 0; pp < 4; pp++) {
                const uint32_t addr = Sb + rowB[pp] * 128 + (((2*ks + khb) ^ rm) * 16);
                LDSM_X4(b[pp][0], b[pp][1], b[pp][2], b[pp][3], addr);
            }
            #pragma unroll
            for (int mi = 0; mi < 4; mi++)
                #pragma unroll
                for (int nj = 0; nj < 8; nj++)
                    mma16(acc[mi][nj], a[mi],
                          b[nj >> 1][(nj & 1) * 2], b[nj >> 1][(nj & 1) * 2 + 1]);
        }
    };

    GDC_WAIT();                         // inputs from convert_all visible
    issue_copy(0, 0); CP_COMMIT();
    issue_copy(1, 1); CP_COMMIT();
    int buf = 0;
    for (int kt = 0; kt < KT; kt++) {
        CP_WAIT1();
        __syncthreads();
        if (kt + 2 < KT) issue_copy(kt + 2, (buf + 2) % NSTAGE);
        CP_COMMIT();
        compute(buf);
        buf = (buf + 1) % NSTAGE;
    }

    const int gr0 = bm * 128 + wm * 64 + (lane >> 2);
    const int gc0 = bn * 128 + wn * 64 + (lane & 3) * 2;
    #pragma unroll
    for (int mi = 0; mi < 4; mi++) {
        #pragma unroll
        for (int half = 0; half < 2; half++) {
            const int row = gr0 + mi * 16 + half * 8;
            float s = 0.f;
            #pragma unroll
            for (int nj = 0; nj < 8; nj++) {
                const int col = gc0 + nj * 8;
                const float v0 = acc[mi][nj][half * 2 + 0];
                const float v1 = acc[mi][nj][half * 2 + 1];
                const __nv_bfloat162 hp = __floats2bfloat162_rn(
                    fmaxf(v0 + prm[col + 0], 0.f),
                    fmaxf(v1 + prm[col + 1], 0.f));
                *(uint32_t*)(C + (size_t)row * N + col) = *(const uint32_t*)&hp;
                const float2 hf = __bfloat1622float2(hp);
                s = fmaf(hf.x, hf.x, fmaf(hf.y, hf.y, s));
            }
            s += __shfl_xor_sync(0xFFFFFFFFu, s, 1);
            s += __shfl_xor_sync(0xFFFFFFFFu, s, 2);
            if ((lane & 3) == 0)
                hpart[(size_t)row * 8 + bn * 2 + wn] = s;
        }
    }
    GDC_LAUNCH();
}

// ---------------------------------------------------------------------------
// GEMM2: t = -log(1 + max(||h||^2 - 2 h@Wq^T + ||w||^2, 0))
// 8 warps (2m x 4n, warp tile 64x32), CTA 128x128, MSUB=2 M-tiles per CTA.
// ||h||^2 finished in-kernel from hpart (8 partials/row) into smem.
// ---------------------------------------------------------------------------
#define MSUB2 2
__global__ __launch_bounds__(256, 2)
void tgemm2(const __nv_bfloat16* __restrict__ A, const __nv_bfloat16* __restrict__ Bm,
            const float* __restrict__ prm, const float* __restrict__ hpart,
            float* __restrict__ C, int M, int N, int K)
{
    extern __shared__ char smem[];
    const uint32_t sbase = smem_u32(smem);
    float* rn_s = (float*)(smem + NSTAGE * STAGE_BYTES);   // 128 floats

    const int tid  = threadIdx.x;
    const int bn   = blockIdx.x;
    const int warp = tid >> 5, lane = tid & 31;
    const int wm   = warp & 1;
    const int wn   = warp >> 1;         // 0..3
    const int rm   = lane & 7;

    const int kha = lane >> 4;
    const int khb = (lane >> 3) & 1;
    int rowA[4], rowB[2];
    #pragma unroll
    for (int mi = 0; mi < 4; mi++)
        rowA[mi] = wm * 64 + mi * 16 + ((lane >> 3) & 1) * 8 + rm;
    #pragma unroll
    for (int pp = 0; pp < 2; pp++)
        rowB[pp] = wn * 32 + pp * 16 + ((lane >> 4) & 1) * 8 + rm;

    const int KT = K >> 6;
    const int r0 = tid >> 3;
    const int c4 = tid & 7;

    GDC_WAIT();                         // h, hpart from tgemm1 visible

    for (int sub = 0; sub < MSUB2; sub++) {
        const int bm = blockIdx.y * MSUB2 + sub;
        __syncthreads();                // protect stage buffers + rn_s

        if (tid < 128) {
            const float4* pp = (const float4*)(hpart + (size_t)(bm * 128 + tid) * 8);
            const float4 a = pp[0], b = pp[1];
            rn_s[tid] = ((a.x + a.y) + (a.z + a.w)) + ((b.x + b.y) + (b.z + b.w));
        }

        float acc[4][4][4];
        #pragma unroll
        for (int i = 0; i < 4; i++)
            #pragma unroll
            for (int j = 0; j < 4; j++)
                #pragma unroll
                for (int q = 0; q < 4; q++) acc[i][j][q] = 0.f;

        auto issue_copy = [&](int kt, int buf) {
            const uint32_t sa = sbase + buf * STAGE_BYTES;
            const uint32_t sb = sa + TILE_BYTES;
            const __nv_bfloat16* ag = A  + (size_t)(bm * 128 + r0) * K + kt * 64 + c4 * 8;
            const __nv_bfloat16* bg = Bm + (size_t)(bn * 128 + r0) * K + kt * 64 + c4 * 8;
            #pragma unroll
            for (int p = 0; p < 4; p++) {
                const int row = r0 + p * 32;
                const uint32_t soff = row * 128 + ((c4 ^ (row & 7)) * 16);
                CP16(sa + soff, ag + (size_t)p * 32 * K);
                CP16(sb + soff, bg + (size_t)p * 32 * K);
            }
        };

        auto compute = [&](int buf) {
            const uint32_t Sa = sbase + buf * STAGE_BYTES;
            const uint32_t Sb = Sa + TILE_BYTES;
            #pragma unroll
            for (int ks = 0; ks < 4; ks++) {
                uint32_t a[4][4], b[2][4];
                #pragma unroll
                for (int mi = 0; mi < 4; mi++) {
                    const uint32_t addr = Sa + rowA[mi] * 128 + (((2*ks + kha) ^ rm) * 16);
                    LDSM_X4(a[mi][0], a[mi][1], a[mi][2], a[mi][3], addr);
                }
                #pragma unroll
                for (int pp = 0; pp < 2; pp++) {
                    const uint32_t addr = Sb + rowB[pp] * 128 + (((2*ks + khb) ^ rm) * 16);
                    LDSM_X4(b[pp][0], b[pp][1], b[pp][2], b[pp][3], addr);
                }
                #pragma unroll
                for (int mi = 0; mi < 4; mi++)
                    #pragma unroll
                    for (int nj = 0; nj < 4; nj++)
                        mma16(acc[mi][nj], a[mi],
                              b[nj >> 1][(nj & 1) * 2], b[nj >> 1][(nj & 1) * 2 + 1]);
            }
        };

        issue_copy(0, 0); CP_COMMIT();
        issue_copy(1, 1); CP_COMMIT();
        int buf = 0;
        for (int kt = 0; kt < KT; kt++) {
            CP_WAIT1();
            __syncthreads();            // also orders rn_s before epilogue
            if (kt + 2 < KT) issue_copy(kt + 2, (buf + 2) % NSTAGE);
            CP_COMMIT();
            compute(buf);
            buf = (buf + 1) % NSTAGE;
        }

        const int lr0 = wm * 64 + (lane >> 2);
        const int gc0 = bn * 128 + wn * 32 + (lane & 3) * 2;
        #pragma unroll
        for (int mi = 0; mi < 4; mi++) {
            #pragma unroll
            for (int half = 0; half < 2; half++) {
                const int lrow = lr0 + mi * 16 + half * 8;
                const int row  = bm * 128 + lrow;
                const float rn = rn_s[lrow];
                float* crow = C + (size_t)row * N;
                #pragma unroll
                for (int nj = 0; nj < 4; nj++) {
                    const int col = gc0 + nj * 8;
                    const float v0 = acc[mi][nj][half * 2 + 0];
                    const float v1 = acc[mi][nj][half * 2 + 1];
                    const float d0 = fmaxf(fmaf(-2.f, v0, rn + prm[col + 0]), 0.f);
                    const float d1 = fmaxf(fmaf(-2.f, v1, rn + prm[col + 1]), 0.f);
                    float2 o = { -__logf(1.f + d0), -__logf(1.f + d1) };
                    *(float2*)(crow + col) = o;
                }
            }
        }
    }
    GDC_LAUNCH();
}

// ---------------------------------------------------------------------------
// Merged fp32->bf16 conversion, 16 elems/thread: x (relu), W_fc, W_q.
// W_q: one warp covers exactly one row (32 lanes x 16 = 512) -> shfl norm.
// Region boundaries are multiples of 4096 elements; blocks never straddle.
// ---------------------------------------------------------------------------
#define NXB_E ((size_t)BB * NX)
#define NFC_E ((size_t)NH * NX)
#define NWQ_E ((size_t)NY * NH)

__global__ __launch_bounds__(256)
void convert_all(const float* __restrict__ x, const float* __restrict__ wfc,
                 const float* __restrict__ wq, __nv_bfloat16* __restrict__ xb,
                 __nv_bfloat16* __restrict__ wfcb, __nv_bfloat16* __restrict__ wqb,
                 float* __restrict__ wqn)
{
    const int tid = threadIdx.x;
    const size_t i = (size_t)blockIdx.x * blockDim.x + tid;
    const size_t e = i * 16;
    const float* src;
    __nv_bfloat16* dst;
    bool relu = false, iswq = false;
    size_t local = 0;
    if (e < NXB_E)              { src = x   + e;           dst = xb   + e;           relu = true; }
    else if (e < NXB_E + NFC_E) { src = wfc + (e - NXB_E); dst = wfcb + (e - NXB_E); }
    else { local = e - NXB_E - NFC_E; src = wq + local; dst = wqb + local; iswq = true; }

    float4 a0 = ((const float4*)src)[0];
    float4 a1 = ((const float4*)src)[1];
    float4 a2 = ((const float4*)src)[2];
    float4 a3 = ((const float4*)src)[3];
    if (relu) {
        a0.x = fmaxf(a0.x, 0.f); a0.y = fmaxf(a0.y, 0.f);
        a0.z = fmaxf(a0.z, 0.f); a0.w = fmaxf(a0.w, 0.f);
        a1.x = fmaxf(a1.x, 0.f); a1.y = fmaxf(a1.y, 0.f);
        a1.z = fmaxf(a1.z, 0.f); a1.w = fmaxf(a1.w, 0.f);
        a2.x = fmaxf(a2.x, 0.f); a2.y = fmaxf(a2.y, 0.f);
        a2.z = fmaxf(a2.z, 0.f); a2.w = fmaxf(a2.w, 0.f);
        a3.x = fmaxf(a3.x, 0.f); a3.y = fmaxf(a3.y, 0.f);
        a3.z = fmaxf(a3.z, 0.f); a3.w = fmaxf(a3.w, 0.f);
    }
    uint4 o0 = { pack_bf16(a0.x, a0.y), pack_bf16(a0.z, a0.w),
                 pack_bf16(a1.x, a1.y), pack_bf16(a1.z, a1.w) };
    uint4 o1 = { pack_bf16(a2.x, a2.y), pack_bf16(a2.z, a2.w),
                 pack_bf16(a3.x, a3.y), pack_bf16(a3.z, a3.w) };
    ((uint4*)dst)[0] = o0;
    ((uint4*)dst)[1] = o1;

    if (iswq) {
        float s = 0.f;
        #pragma unroll
        for (int q = 0; q < 4; q++) {
            const float2 v0 = __bfloat1622float2(*(const __nv_bfloat162*)&(&o0.x)[q]);
            const float2 v1 = __bfloat1622float2(*(const __nv_bfloat162*)&(&o1.x)[q]);
            s = fmaf(v0.x, v0.x, fmaf(v0.y, v0.y, s));
            s = fmaf(v1.x, v1.x, fmaf(v1.y, v1.y, s));
        }
        #pragma unroll
        for (int off = 16; off; off >>= 1)
            s += __shfl_xor_sync(0xFFFFFFFFu, s, off);
        if ((tid & 31) == 0)
            wqn[local >> 9] = s;        // 512 elems per W_q row = 1 warp
    }
    GDC_LAUNCH();
}

// ---------------------------------------------------------------------------
// One-pass log-softmax: HALF row per warp (2048 blocks -> better latency
// hiding than 1 row/warp). Warp pairs combine exp-sums via smem; addition is
// commutative so both warps compute the identical total. t in [-8, 0] so
// exp() cannot overflow/underflow; no max pass needed.
// ---------------------------------------------------------------------------
__global__ __launch_bounds__(256)
void lse_kernel(float* __restrict__ T)
{
    __shared__ float sred[8];
    const int warp = threadIdx.x >> 5, lane = threadIdx.x & 31;
    const int hid  = blockIdx.x * 8 + warp;   // half-row id
    const int row  = hid >> 1, half = hid & 1;
    float* t = T + (size_t)row * NY + half * (NY / 2);

    GDC_WAIT();

    float4 v[4];
    #pragma unroll
    for (int i = 0; i < 4; i++)
        v[i] = *(const float4*)(t + (lane + i * 32) * 4);

    float s = 0.f;
    #pragma unroll
    for (int i = 0; i < 4; i++)
        s += __expf(v[i].x) + __expf(v[i].y) + __expf(v[i].z) + __expf(v[i].w);
    #pragma unroll
    for (int o = 16; o; o >>= 1) s += __shfl_xor_sync(0xFFFFFFFFu, s, o);
    if (lane == 0) sred[warp] = s;
    __syncthreads();
    const float lse = __logf(sred[warp] + sred[warp ^ 1]);

    #pragma unroll
    for (int i = 0; i < 4; i++) {
        float4 o4 = { v[i].x - lse, v[i].y - lse, v[i].z - lse, v[i].w - lse };
        *(float4*)(t + (lane + i * 32) * 4) = o4;
    }
}

// ---------------------------------------------------------------------------
extern "C" void kernel_launch(void* const* d_in, const int* in_sizes, int n_in,
                              void* d_out, int out_size)
{
    const float* x    = (const float*)d_in[0];   // [B, Nx]
    const float* W_fc = (const float*)d_in[1];   // [Nh, Nx]
    const float* b_fc = (const float*)d_in[2];   // [Nh]
    const float* W_q  = (const float*)d_in[3];   // [Ny, Nh]
    float* out = (float*)d_out;                  // [B, Ny]

    void* p;
    cudaGetSymbolAddress(&p, g_xb);     __nv_bfloat16* xb   = (__nv_bfloat16*)p;
    cudaGetSymbolAddress(&p, g_wfcb);   __nv_bfloat16* wfcb = (__nv_bfloat16*)p;
    cudaGetSymbolAddress(&p, g_wqb);    __nv_bfloat16* wqb  = (__nv_bfloat16*)p;
    cudaGetSymbolAddress(&p, g_hb);     __nv_bfloat16* hb   = (__nv_bfloat16*)p;
    cudaGetSymbolAddress(&p, g_hpart);  float* hp  = (float*)p;
    cudaGetSymbolAddress(&p, g_wqnorm); float* wqn = (float*)p;

    cudaFuncSetAttribute(tgemm1, cudaFuncAttributeMaxDynamicSharedMemorySize, DSMEM_BYTES);
    cudaFuncSetAttribute(tgemm2, cudaFuncAttributeMaxDynamicSharedMemorySize, DSMEM_BYTES);

    cudaLaunchAttribute pdl[1];
    pdl[0].id = cudaLaunchAttributeProgrammaticStreamSerialization;
    pdl[0].val.programmaticStreamSerializationAllowed = 1;

    // 0) convert all inputs to bf16 (relu fused into x; wq norms fused)
    {
        const size_t total = NXB_E + NFC_E + NWQ_E;
        convert_all<<<(unsigned)(total / 4096), 256>>>(x, W_fc, W_q, xb, wfcb, wqb, wqn);
    }
    // 1) h = relu(xb @ wfcb^T + b_fc) -> bf16, plus ||h||^2 partials [PDL]
    {
        cudaLaunchConfig_t cfg = {};
        cfg.gridDim  = dim3(NH / 128, BB / 128, 1);
        cfg.blockDim = dim3(128, 1, 1);
        cfg.dynamicSmemBytes = DSMEM_BYTES;
        cfg.attrs = pdl; cfg.numAttrs = 1;
        cudaLaunchKernelEx(&cfg, tgemm1,
                           (const __nv_bfloat16*)xb, (const __nv_bfloat16*)wfcb,
                           (const float*)b_fc, hp, hb, (int)BB, (int)NH, (int)NX);
    }
    // 2) t = -log(1 + max(||h||^2 - 2 h@Wq^T + ||w||^2, 0)) [PDL]
    {
        cudaLaunchConfig_t cfg = {};
        cfg.gridDim  = dim3(NY / 128, BB / 256, 1);
        cfg.blockDim = dim3(256, 1, 1);
        cfg.dynamicSmemBytes = DSMEM_BYTES;
        cfg.attrs = pdl; cfg.numAttrs = 1;
        cudaLaunchKernelEx(&cfg, tgemm2,
                           (const __nv_bfloat16*)hb, (const __nv_bfloat16*)wqb,
                           (const float*)wqn, (const float*)hp, out,
                           (int)BB, (int)NY, (int)NH);
    }
    // 3) log-softmax normalization, half-row per warp [PDL]
    {
        cudaLaunchConfig_t cfg = {};
        cfg.gridDim  = dim3(BB * 2 / 8, 1, 1);
        cfg.blockDim = dim3(256, 1, 1);
        cfg.attrs = pdl; cfg.numAttrs = 1;
        cudaLaunchKernelEx(&cfg, lse_kernel, out);
    }
}